// round 2
// baseline (speedup 1.0000x reference)
#include <cuda_runtime.h>
#include <cuda_bf16.h>
#include <math.h>

// Problem constants (from reference)
#define NUM_POS_FEATS 64          // F
#define N_AXES 3
#define MAX_COORD 128             // SPATIAL dims are all 128
#define TABLE_ELEMS (N_AXES * MAX_COORD * NUM_POS_FEATS)   // 24576 floats = 96 KB

// Lookup table: table[(c*128 + q)*64 + f]
//   f even: sin(q_norm_c / dim_t[f]),  f odd: cos(q_norm_c / dim_t[f])
//   dim_t[f] = 10000^(2*floor(f/2)/64),  q_norm_c = q/(S_c-1+eps)*2*pi
__device__ float g_table[TABLE_ELEMS];

__global__ void build_table_kernel(const int* __restrict__ sx,
                                   const int* __restrict__ sy,
                                   const int* __restrict__ sz) {
    int idx = blockIdx.x * blockDim.x + threadIdx.x;
    if (idx >= TABLE_ELEMS) return;
    int c   = idx / (MAX_COORD * NUM_POS_FEATS);
    int rem = idx - c * (MAX_COORD * NUM_POS_FEATS);
    int q   = rem / NUM_POS_FEATS;
    int f   = rem - q * NUM_POS_FEATS;

    int S = (c == 0) ? *sx : (c == 1) ? *sy : *sz;

    // match reference: vals = q / (S-1+eps) * 2*pi ; p = vals / dim_t
    double denom = (double)(S - 1) + 1.0e-06;
    double val   = ((double)q / denom) * (2.0 * M_PI);
    double dt    = pow(10000.0, (double)(f >> 1) * (2.0 / (double)NUM_POS_FEATS));
    double p     = val / dt;
    g_table[idx] = (float)((f & 1) ? cos(p) : sin(p));
}

// One thread per output float4. 192 floats per point = 48 float4s:
//   quad index g: m = g/48, r = g%48, axis c = r/16, quad-in-axis fq = r%16
// Output row == input row (b is sorted repeat(arange), slot = m % max_len),
// so no scatter: fully coalesced streaming stores.
__global__ void __launch_bounds__(256) fill_kernel(const int* __restrict__ coords,
                                                   float4* __restrict__ out,
                                                   int total_quads) {
    int g = blockIdx.x * blockDim.x + threadIdx.x;
    if (g >= total_quads) return;

    unsigned ug = (unsigned)g;
    unsigned m  = ug / 48u;
    unsigned r  = ug - m * 48u;
    unsigned c  = r >> 4;          // 0..2
    unsigned fq = r & 15u;         // 0..15 (quad within the 64-feature axis block)

    int q = __ldg(&coords[m * 4u + 1u + c]);   // integer coordinate, 0..127

    const float4* tbl = reinterpret_cast<const float4*>(g_table);
    float4 v = tbl[(c * (unsigned)MAX_COORD + (unsigned)q) * 16u + fq];

    out[ug] = v;
}

extern "C" void kernel_launch(void* const* d_in, const int* in_sizes, int n_in,
                              void* d_out, int out_size) {
    const int* coords = (const int*)d_in[0];
    const int* sx = (const int*)d_in[1];
    const int* sy = (const int*)d_in[2];
    const int* sz = (const int*)d_in[3];
    (void)n_in;

    int M = in_sizes[0] / 4;                    // points
    int total_quads = M * 48;                   // (M * 192) / 4

    // Kernel 1: build the 96 KB sin/cos lookup table (24576 threads, trivial)
    build_table_kernel<<<(TABLE_ELEMS + 255) / 256, 256>>>(sx, sy, sz);

    // Kernel 2: gather from table (L1-resident) + coalesced float4 streaming stores
    fill_kernel<<<(total_quads + 255) / 256, 256>>>(coords, (float4*)d_out,
                                                    total_quads);
    (void)out_size;
}

// round 8
// speedup vs baseline: 1.6745x; 1.6745x over previous
#include <cuda_runtime.h>
#include <cuda_bf16.h>
#include <math.h>

// Problem constants (from reference)
#define NUM_POS_FEATS 64          // F
#define N_AXES 3
#define MAX_COORD 128             // SPATIAL dims are all 128
#define TABLE_ELEMS (N_AXES * MAX_COORD * NUM_POS_FEATS)   // 24576 floats = 96 KB

// Lookup table: table[(c*128 + q)*64 + f]
//   f even: sin(q_norm_c / dim_t[f]),  f odd: cos(q_norm_c / dim_t[f])
__device__ float g_table[TABLE_ELEMS];

// All-fp32 table build: rel-err budget is 1e-3, fp32 sinf/cosf give ~1e-7.
// Avoids the fp64 pipe (R2 burned ~14us of fp64 transcendentals here).
__global__ void build_table_kernel(const int* __restrict__ sx,
                                   const int* __restrict__ sy,
                                   const int* __restrict__ sz) {
    int idx = blockIdx.x * blockDim.x + threadIdx.x;
    if (idx >= TABLE_ELEMS) return;
    int c   = idx / (MAX_COORD * NUM_POS_FEATS);
    int rem = idx - c * (MAX_COORD * NUM_POS_FEATS);
    int q   = rem / NUM_POS_FEATS;
    int f   = rem - q * NUM_POS_FEATS;

    int S = (c == 0) ? *sx : (c == 1) ? *sy : *sz;

    // vals = q/(S-1+eps) * 2*pi ; dim_t = 10000^(2*(f/2)/64) ; p = vals/dim_t
    float denom = (float)(S - 1) + 1.0e-06f;
    float val   = ((float)q / denom) * 6.2831853071795864769f;
    // 10000^x = 2^(x*log2(10000)), x = (f>>1)/32
    float ex    = (float)(f >> 1) * (13.287712379549449f / 32.0f);
    float dt    = exp2f(ex);
    float p     = val / dt;
    g_table[idx] = (f & 1) ? cosf(p) : sinf(p);
}

// Warp-stride unroll-4: each warp owns 128 consecutive output float4s.
// Lane l handles quads base+l, base+l+32, base+l+64, base+l+96 -> every STG
// is a fully-coalesced 512B warp write, and the 4 iterations are independent
// (MLP=4: ptxas front-batches 4 coords LDGs, then 4 table LDGs, then 4 STGs).
__global__ void __launch_bounds__(256) fill_kernel(const int* __restrict__ coords,
                                                   float4* __restrict__ out,
                                                   int total_quads) {
    const unsigned warp_id = (unsigned)(blockIdx.x * (blockDim.x >> 5) + (threadIdx.x >> 5));
    const unsigned lane    = threadIdx.x & 31u;
    const unsigned base    = warp_id * 128u + lane;

    const float4* tbl = reinterpret_cast<const float4*>(g_table);

#pragma unroll
    for (int i = 0; i < 4; i++) {
        unsigned g = base + (unsigned)i * 32u;
        if (g < (unsigned)total_quads) {
            unsigned m  = g / 48u;           // point index
            unsigned r  = g - m * 48u;
            unsigned c  = r >> 4;            // axis 0..2
            unsigned fq = r & 15u;           // float4 within the 64-feature block

            int q = __ldg(&coords[m * 4u + 1u + c]);   // 0..127

            out[g] = tbl[(c * (unsigned)MAX_COORD + (unsigned)q) * 16u + fq];
        }
    }
}

extern "C" void kernel_launch(void* const* d_in, const int* in_sizes, int n_in,
                              void* d_out, int out_size) {
    const int* coords = (const int*)d_in[0];
    const int* sx = (const int*)d_in[1];
    const int* sy = (const int*)d_in[2];
    const int* sz = (const int*)d_in[3];
    (void)n_in;

    int M = in_sizes[0] / 4;                    // number of points
    int total_quads = M * 48;                   // (M*192)/4 float4s

    build_table_kernel<<<(TABLE_ELEMS + 255) / 256, 256>>>(sx, sy, sz);

    // 128 quads per warp, 8 warps per block -> 1024 quads per block
    int n_blocks = (total_quads + 1023) / 1024;
    fill_kernel<<<n_blocks, 256>>>(coords, (float4*)d_out, total_quads);
    (void)out_size;
}

// round 9
// speedup vs baseline: 1.8601x; 1.1108x over previous
#include <cuda_runtime.h>
#include <cuda_bf16.h>
#include <math.h>

// Problem constants (from reference)
#define NUM_POS_FEATS 64          // F
#define N_AXES 3
#define MAX_COORD 128             // SPATIAL dims are all 128
#define TABLE_ELEMS (N_AXES * MAX_COORD * NUM_POS_FEATS)   // 24576 floats = 96 KB

// Lookup table: table[(c*128 + q)*64 + f]
//   f even: sin(q_norm_c / dim_t[f]),  f odd: cos(q_norm_c / dim_t[f])
__device__ float g_table[TABLE_ELEMS];

// All-fp32 table build: rel-err budget is 1e-3, fp32 sinf/cosf give ~1e-7.
__global__ void build_table_kernel(const int* __restrict__ sx,
                                   const int* __restrict__ sy,
                                   const int* __restrict__ sz) {
    int idx = blockIdx.x * blockDim.x + threadIdx.x;
    if (idx >= TABLE_ELEMS) return;
    int c   = idx / (MAX_COORD * NUM_POS_FEATS);
    int rem = idx - c * (MAX_COORD * NUM_POS_FEATS);
    int q   = rem / NUM_POS_FEATS;
    int f   = rem - q * NUM_POS_FEATS;

    int S = (c == 0) ? *sx : (c == 1) ? *sy : *sz;

    // vals = q/(S-1+eps) * 2*pi ; dim_t = 10000^(2*(f/2)/64) ; p = vals/dim_t
    float denom = (float)(S - 1) + 1.0e-06f;
    float val   = ((float)q / denom) * 6.2831853071795864769f;
    // 10000^x = 2^(x*log2(10000)), x = (f>>1)/32
    float ex    = (float)(f >> 1) * (13.287712379549449f / 32.0f);
    float dt    = exp2f(ex);
    float p     = val / dt;
    g_table[idx] = (f & 1) ? cosf(p) : sinf(p);
}

// Warp-stride unroll-8: each warp owns 256 consecutive output float4s.
// Lane l handles quads base+l+32*i (i=0..7) -> every STG is a fully-coalesced
// 512B warp write, and the 8 iterations are independent chains (MLP=8):
// ptxas front-batches 8 coords LDGs, then 8 table LDGs, then 8 STGs.
// Stores use __stcs (evict-first): output (251.6MB) exceeds L2 (126MB), so
// retaining dirty output lines only thrashes L2 against table reads.
__global__ void __launch_bounds__(256) fill_kernel(const int* __restrict__ coords,
                                                   float4* __restrict__ out,
                                                   int total_quads) {
    const unsigned warp_id = (unsigned)(blockIdx.x * (blockDim.x >> 5) + (threadIdx.x >> 5));
    const unsigned lane    = threadIdx.x & 31u;
    const unsigned base    = warp_id * 256u + lane;

    const float4* tbl = reinterpret_cast<const float4*>(g_table);

#pragma unroll
    for (int i = 0; i < 8; i++) {
        unsigned g = base + (unsigned)i * 32u;
        if (g < (unsigned)total_quads) {
            unsigned m  = g / 48u;           // point index
            unsigned r  = g - m * 48u;
            unsigned c  = r >> 4;            // axis 0..2
            unsigned fq = r & 15u;           // float4 within the 64-feature block

            int q = __ldg(&coords[m * 4u + 1u + c]);   // 0..127

            float4 v = tbl[(c * (unsigned)MAX_COORD + (unsigned)q) * 16u + fq];
            __stcs(&out[g], v);              // streaming store, evict-first
        }
    }
}

extern "C" void kernel_launch(void* const* d_in, const int* in_sizes, int n_in,
                              void* d_out, int out_size) {
    const int* coords = (const int*)d_in[0];
    const int* sx = (const int*)d_in[1];
    const int* sy = (const int*)d_in[2];
    const int* sz = (const int*)d_in[3];
    (void)n_in;

    int M = in_sizes[0] / 4;                    // number of points
    int total_quads = M * 48;                   // (M*192)/4 float4s

    build_table_kernel<<<(TABLE_ELEMS + 255) / 256, 256>>>(sx, sy, sz);

    // 256 quads per warp, 8 warps per block -> 2048 quads per block
    int n_blocks = (total_quads + 2047) / 2048;
    fill_kernel<<<n_blocks, 256>>>(coords, (float4*)d_out, total_quads);
    (void)out_size;
}